// round 7
// baseline (speedup 1.0000x reference)
#include <cuda_runtime.h>
#include <cuda_bf16.h>
#include <cstdint>

#define Bz  8
#define Nn  8192
#define Dm  256
#define Hh  4
#define Rr  64
#define HDd 64
#define Mm  (Bz*Nn)

typedef unsigned long long u64;

// ---------------- device scratch ----------------
__device__ float g_bK[Dm];
__device__ float g_xv[(size_t)Mm*Dm];                 // fp32 xv (exact gate term)
__device__ __nv_bfloat16 g_eb  [(size_t)Mm*Dm];       // bf16 raw exp(attn)
__device__ __nv_bfloat16 g_xvsb[(size_t)Mm*Dm];       // bf16 xv / rs[n,h]
__device__ float g_rs[(size_t)Mm*Hh];                 // fp32 rowsum of e per (n,h)
__device__ float g_pool[Bz*Hh*Rr*HDd];                // fp32 P0 accumulator
__device__ __nv_bfloat16 g_poolb[Bz*Hh*Rr*HDd];       // bf16 P0/S
__device__ float g_S [Bz*Hh*Rr];
__device__ __nv_bfloat16 g_Wh[2][Dm*Dm];              // bf16 hi image of W ([k][n])
__device__ __nv_bfloat16 g_Wl[2][Dm*Dm];              // bf16 lo image

// ---------------- helpers ----------------
__device__ __forceinline__ void cpa16(uint32_t d, const void* s) {
    asm volatile("cp.async.cg.shared.global [%0], [%1], 16;" :: "r"(d), "l"(s));
}
#define CPCOMMIT() asm volatile("cp.async.commit_group;")
#define CPWAIT0()  asm volatile("cp.async.wait_group 0;")

__device__ __forceinline__ void ldsm4(uint32_t* r, uint32_t a) {
    asm volatile("ldmatrix.sync.aligned.m8n8.x4.shared.b16 {%0,%1,%2,%3}, [%4];"
        : "=r"(r[0]), "=r"(r[1]), "=r"(r[2]), "=r"(r[3]) : "r"(a));
}
__device__ __forceinline__ void ldsm4t(uint32_t* r, uint32_t a) {
    asm volatile("ldmatrix.sync.aligned.m8n8.x4.trans.shared.b16 {%0,%1,%2,%3}, [%4];"
        : "=r"(r[0]), "=r"(r[1]), "=r"(r[2]), "=r"(r[3]) : "r"(a));
}
__device__ __forceinline__ void hmma(float* c, const uint32_t* a, uint32_t b0, uint32_t b1) {
    asm volatile("mma.sync.aligned.m16n8k16.row.col.f32.bf16.bf16.f32 "
        "{%0,%1,%2,%3}, {%4,%5,%6,%7}, {%8,%9}, {%0,%1,%2,%3};"
        : "+f"(c[0]), "+f"(c[1]), "+f"(c[2]), "+f"(c[3])
        : "r"(a[0]), "r"(a[1]), "r"(a[2]), "r"(a[3]), "r"(b0), "r"(b1));
}
__device__ __forceinline__ uint2 f4_to_bf16x4(float4 v) {
    uint32_t a, b;
    asm("cvt.rn.bf16x2.f32 %0, %1, %2;" : "=r"(a) : "f"(v.y), "f"(v.x));
    asm("cvt.rn.bf16x2.f32 %0, %1, %2;" : "=r"(b) : "f"(v.w), "f"(v.z));
    return make_uint2(a, b);
}

// ---------------- small kernels ----------------
__global__ void kzero() {
    int i = blockIdx.x*blockDim.x + threadIdx.x;
    if (i < Bz*Hh*Rr*HDd) g_pool[i] = 0.f;
    if (i < Bz*Hh*Rr)     g_S[i]   = 0.f;
}

// fold Wq@K -> WK, emit bf16 hi/lo split directly; fold bias
__global__ void kprep(const float* __restrict__ Wq, const float* __restrict__ bq,
                      const float* __restrict__ K) {
    int col = threadIdx.x;
    int h = col >> 6, r = col & 63;
    const float* Krow = K + r*Dm + h*HDd;
    if (blockIdx.x < Dm) {
        int c = blockIdx.x;
        const float* wq = Wq + c*Dm + h*HDd;
        float s = 0.f;
        #pragma unroll 16
        for (int d = 0; d < HDd; d++) s = fmaf(wq[d], Krow[d], s);
        s *= 0.125f;
        __nv_bfloat16 hi = __float2bfloat16(s);
        g_Wh[1][c*Dm + col] = hi;
        g_Wl[1][c*Dm + col] = __float2bfloat16(s - __bfloat162float(hi));
    } else {
        float s = 0.f;
        #pragma unroll 16
        for (int d = 0; d < HDd; d++) s = fmaf(bq[h*HDd + d], Krow[d], s);
        g_bK[col] = 0.125f * s;
    }
}

__global__ void kprep2(const float* __restrict__ Wv) {
    int k = blockIdx.x, n = threadIdx.x;
    float wv = Wv[(size_t)k*Dm + n];
    __nv_bfloat16 hi = __float2bfloat16(wv);
    g_Wh[0][k*Dm + n] = hi;
    g_Wl[0][k*Dm + n] = __float2bfloat16(wv - __bfloat162float(hi));
}

// ---------------- HMMA GEMM: C[128,256] per CTA, K=256, double-buffered ----------------
// smem: A stage s: hi @ s*36864, lo @ s*36864+18432 (128 rows x 144B each)
//       B stage s: hi @ 73728+s*67584, lo @ +33792   (64 rows x 528B each)
// after mainloop: C fp32 [128][268] @0 (137216B), rs [128][4] @137216
#define A_BASE(s) ((s)*36864)
#define A_LO      18432
#define B_BASE(s) (73728 + (s)*67584)
#define B_LO      33792
#define C_STRIDE  268
#define RS2_OFF   137216
#define SMEM_MMA  208896

__global__ void __launch_bounds__(512, 1)
kgemm_mma(const float* __restrict__ A, const float* __restrict__ bias, int gemm) {
    extern __shared__ char sm[];
    uint32_t smb = (uint32_t)__cvta_generic_to_shared(sm);
    const int t = threadIdx.x, w = t >> 5, lane = t & 31;
    const int m0 = blockIdx.x*128;
    const __nv_bfloat16* Wh = g_Wh[gemm];
    const __nv_bfloat16* Wl = g_Wl[gemm];
    const float* bp = gemm ? g_bK : bias;
    const int wm = (w >> 2)*32, wn = (w & 3)*64;

    float acc[2][8][4];
    #pragma unroll
    for (int i = 0; i < 2; i++)
        #pragma unroll
        for (int j = 0; j < 8; j++)
            #pragma unroll
            for (int q = 0; q < 4; q++) acc[i][j][q] = 0.f;

    // ---- staging lambdas (macros) ----
#define STAGE_B(kc, s)                                                        \
    {                                                                         \
        const __nv_bfloat16* srcH = Wh + (size_t)((kc)*64)*Dm;                \
        const __nv_bfloat16* srcL = Wl + (size_t)((kc)*64)*Dm;                \
        _Pragma("unroll")                                                     \
        for (int p = 0; p < 4; p++) {                                         \
            int idx = t + p*512;                                              \
            int row = idx >> 5, off = idx & 31;                               \
            uint32_t d = smb + B_BASE(s) + (uint32_t)(row*528 + off*16);      \
            cpa16(d,        srcH + (size_t)row*Dm + off*8);                   \
            cpa16(d + B_LO, srcL + (size_t)row*Dm + off*8);                   \
        }                                                                     \
        CPCOMMIT();                                                           \
    }
#define STAGE_A(kc, s)                                                        \
    {                                                                         \
        int row = t >> 2, q = t & 3;                                          \
        const float4* ar = (const float4*)(A + (size_t)(m0 + row)*Dm + (kc)*64 + q*16); \
        char* wbH = sm + A_BASE(s) + row*144 + q*32;                          \
        char* wbL = wbH + A_LO;                                               \
        _Pragma("unroll")                                                     \
        for (int j4 = 0; j4 < 4; j4++) {                                      \
            float4 v = ar[j4];                                                \
            uint32_t h01, h23, q01, q23;                                      \
            asm("cvt.rn.bf16x2.f32 %0, %1, %2;" : "=r"(h01) : "f"(v.y), "f"(v.x)); \
            asm("cvt.rn.bf16x2.f32 %0, %1, %2;" : "=r"(h23) : "f"(v.w), "f"(v.z)); \
            float l0 = v.x - __uint_as_float(h01 << 16);                      \
            float l1 = v.y - __uint_as_float(h01 & 0xffff0000u);              \
            float l2 = v.z - __uint_as_float(h23 << 16);                      \
            float l3 = v.w - __uint_as_float(h23 & 0xffff0000u);              \
            asm("cvt.rn.bf16x2.f32 %0, %1, %2;" : "=r"(q01) : "f"(l1), "f"(l0)); \
            asm("cvt.rn.bf16x2.f32 %0, %1, %2;" : "=r"(q23) : "f"(l3), "f"(l2)); \
            *(uint2*)(wbH + j4*8) = make_uint2(h01, h23);                     \
            *(uint2*)(wbL + j4*8) = make_uint2(q01, q23);                     \
        }                                                                     \
    }

    STAGE_B(0, 0);
    STAGE_A(0, 0);

    for (int kc = 0; kc < 4; kc++) {
        int s = kc & 1;
        CPWAIT0();
        __syncthreads();
        if (kc < 3) {
            STAGE_B(kc + 1, s ^ 1);
            STAGE_A(kc + 1, s ^ 1);
        }
        // compute chunk from buffer s
        uint32_t aoff = smb + A_BASE(s) + (uint32_t)((wm + (lane & 15))*144) + (lane >> 4)*16;
        uint32_t boff = smb + B_BASE(s) + (uint32_t)((lane & 15)*528) + (uint32_t)((wn + (lane >> 4)*8)*2);
        #pragma unroll
        for (int ks = 0; ks < 4; ks++) {
            uint32_t ah[2][4], al[2][4];
            uint32_t ab = aoff + ks*32;
            ldsm4(ah[0], ab);
            ldsm4(ah[1], ab + 16*144);
            ldsm4(al[0], ab + A_LO);
            ldsm4(al[1], ab + A_LO + 16*144);
            uint32_t bb = boff + ks*16*528;
            #pragma unroll
            for (int nq = 0; nq < 4; nq++) {
                uint32_t bh[4], bl[4];
                ldsm4t(bh, bb + nq*32);
                ldsm4t(bl, bb + nq*32 + B_LO);
                #pragma unroll
                for (int mt = 0; mt < 2; mt++) {
                    #pragma unroll
                    for (int sub = 0; sub < 2; sub++) {
                        float* c = acc[mt][nq*2 + sub];
                        hmma(c, ah[mt], bh[sub*2], bh[sub*2+1]);
                        hmma(c, al[mt], bh[sub*2], bh[sub*2+1]);
                        hmma(c, ah[mt], bl[sub*2], bl[sub*2+1]);
                    }
                }
            }
        }
        __syncthreads();
    }

    // ---- epilogue: C through smem (coalesced), fused bias/exp/rowsum ----
    float* Cs = (float*)sm;
    #pragma unroll
    for (int mt = 0; mt < 2; mt++)
        #pragma unroll
        for (int j = 0; j < 8; j++) {
            int r = wm + mt*16 + (lane >> 2);
            int c = wn + j*8 + (lane & 3)*2;
            *(float2*)&Cs[r*C_STRIDE + c]     = make_float2(acc[mt][j][0], acc[mt][j][1]);
            *(float2*)&Cs[(r+8)*C_STRIDE + c] = make_float2(acc[mt][j][2], acc[mt][j][3]);
        }
    float* rsS = (float*)(sm + RS2_OFF);
    if (gemm == 0)
        rsS[t] = g_rs[(size_t)(m0 + (t >> 2))*Hh + (t & 3)];
    __syncthreads();

    float4 b4[2];
    b4[0] = *(const float4*)(bp + lane*4);
    b4[1] = *(const float4*)(bp + 128 + lane*4);
    #pragma unroll
    for (int p = 0; p < 8; p++) {
        int row = p*16 + w;
        size_t grow = (size_t)(m0 + row)*Dm;
        #pragma unroll
        for (int half = 0; half < 2; half++) {
            int col = half*128 + lane*4;
            int head = half*2 + (lane >> 4);
            float4 v = *(const float4*)&Cs[row*C_STRIDE + col];
            v.x += b4[half].x; v.y += b4[half].y; v.z += b4[half].z; v.w += b4[half].w;
            if (gemm == 0) {
                *(float4*)(g_xv + grow + col) = v;
                float inv = 1.f / rsS[row*4 + head];
                float4 sv = {v.x*inv, v.y*inv, v.z*inv, v.w*inv};
                *(uint2*)(g_xvsb + grow + col) = f4_to_bf16x4(sv);
            } else {
                v.x = __expf(v.x); v.y = __expf(v.y);
                v.z = __expf(v.z); v.w = __expf(v.w);
                float s = v.x + v.y + v.z + v.w;
                s += __shfl_xor_sync(0xffffffffu, s, 1);
                s += __shfl_xor_sync(0xffffffffu, s, 2);
                s += __shfl_xor_sync(0xffffffffu, s, 4);
                s += __shfl_xor_sync(0xffffffffu, s, 8);
                *(uint2*)(g_eb + grow + col) = f4_to_bf16x4(v);
                if ((lane & 15) == 0)
                    g_rs[(size_t)(m0 + row)*Hh + head] = s;
            }
        }
    }
}

// ---------------- kpool: P0[r,d] = sum_n e_bf * xvs_bf  (HMMA) ----------------
__global__ void __launch_bounds__(256, 4) kpool() {
    __shared__ char smE[64*144];
    __shared__ char smX[64*144];
    uint32_t sE = (uint32_t)__cvta_generic_to_shared(smE);
    uint32_t sX = (uint32_t)__cvta_generic_to_shared(smX);
    const int t = threadIdx.x, w = t >> 5, lane = t & 31;
    const int ch = blockIdx.x, h = blockIdx.y, b = blockIdx.z;
    const int r_base = (w & 3)*16, d_base = (w >> 2)*32;
    float acc[4][4];
    #pragma unroll
    for (int i = 0; i < 4; i++)
        #pragma unroll
        for (int q = 0; q < 4; q++) acc[i][q] = 0.f;
    float Sacc = 0.f;

    uint32_t aoff = sE + (uint32_t)((((lane >> 4) << 3) + (lane & 7))*144)
                  + (uint32_t)((r_base + (((lane >> 3) & 1) << 3))*2);
    uint32_t boff = sX + (uint32_t)((lane & 15)*144) + (uint32_t)((d_base + (lane >> 4)*8)*2);

    for (int tile = 0; tile < 16; tile++) {
        int n0 = ch*1024 + tile*64;
        size_t gbase = ((size_t)(b*Nn + n0))*Dm + h*64;
        #pragma unroll
        for (int p = 0; p < 2; p++) {
            int c = t + p*256;
            int row = c >> 3, off = c & 7;
            cpa16(sE + row*144 + off*16, g_eb   + gbase + (size_t)row*Dm + off*8);
            cpa16(sX + row*144 + off*16, g_xvsb + gbase + (size_t)row*Dm + off*8);
        }
        CPCOMMIT();
        CPWAIT0();
        __syncthreads();

        if (t < 64) {
            const __nv_bfloat16* Eb = (const __nv_bfloat16*)smE;
            float s = 0.f;
            #pragma unroll 8
            for (int n = 0; n < 64; n++) s += __bfloat162float(Eb[n*72 + t]);
            Sacc += s;
        }
        #pragma unroll
        for (int ks = 0; ks < 4; ks++) {
            uint32_t a[4];
            ldsm4t(a, aoff + ks*16*144);
            #pragma unroll
            for (int dq = 0; dq < 2; dq++) {
                uint32_t bf[4];
                ldsm4t(bf, boff + ks*16*144 + dq*32);
                hmma(acc[dq*2],   a, bf[0], bf[1]);
                hmma(acc[dq*2+1], a, bf[2], bf[3]);
            }
        }
        __syncthreads();
    }
    float* pp = g_pool + ((size_t)(b*Hh + h)*Rr)*HDd;
    #pragma unroll
    for (int i = 0; i < 4; i++) {
        int r = r_base + (lane >> 2);
        int d = d_base + i*8 + (lane & 3)*2;
        atomicAdd(&pp[r*HDd + d],       acc[i][0]);
        atomicAdd(&pp[r*HDd + d + 1],   acc[i][1]);
        atomicAdd(&pp[(r+8)*HDd + d],   acc[i][2]);
        atomicAdd(&pp[(r+8)*HDd + d+1], acc[i][3]);
    }
    if (t < 64) atomicAdd(&g_S[(b*Hh + h)*Rr + t], Sacc);
}

// ---------------- kfin: poolb = bf16(P0 / S) ----------------
__global__ void kfin() {
    int row = blockIdx.x*256 + threadIdx.x;
    float inv = 1.f / g_S[row];
    const float4* p = (const float4*)(g_pool + (size_t)row*HDd);
    uint2* q = (uint2*)(g_poolb + (size_t)row*HDd);
    #pragma unroll
    for (int i = 0; i < 16; i++) {
        float4 v = p[i];
        v.x *= inv; v.y *= inv; v.z *= inv; v.w *= inv;
        q[i] = f4_to_bf16x4(v);
    }
}

// ---------------- kout: out = sa*xv + sb*(E · P)  (HMMA per head) ----------------
#define KO_E  0                  // 64 rows x 528B
#define KO_P  33792              // 256 rows x 144B
#define SMEM_KOUT 70656
__global__ void __launch_bounds__(256)
kout(const float* __restrict__ alpha, const float* __restrict__ beta,
     float* __restrict__ out) {
    extern __shared__ char sm[];
    uint32_t smb = (uint32_t)__cvta_generic_to_shared(sm);
    const int t = threadIdx.x, w = t >> 5, lane = t & 31;
    const int b = blockIdx.x >> 7;
    const int n0 = (blockIdx.x & 127)*64;
    const int hw = w & 3, m_base = (w >> 2)*32;
    size_t gbase = ((size_t)(b*Nn + n0))*Dm;

    #pragma unroll
    for (int p = 0; p < 8; p++) {
        int c = t + p*256;
        int row = c >> 5, off = c & 31;
        cpa16(smb + KO_E + row*528 + off*16, g_eb + gbase + (size_t)row*Dm + off*8);
        int prow = c >> 3, poff = c & 7;
        cpa16(smb + KO_P + prow*144 + poff*16,
              g_poolb + (size_t)b*(Hh*Rr*HDd) + prow*64 + poff*8);
    }
    CPCOMMIT();
    CPWAIT0();
    __syncthreads();

    float acc[2][8][4];
    #pragma unroll
    for (int i = 0; i < 2; i++)
        #pragma unroll
        for (int j = 0; j < 8; j++)
            #pragma unroll
            for (int q = 0; q < 4; q++) acc[i][j][q] = 0.f;

    uint32_t aoff = smb + KO_E + (uint32_t)((m_base + (lane & 15))*528)
                  + (uint32_t)(hw*128) + (lane >> 4)*16;
    uint32_t boff = smb + KO_P + (uint32_t)(hw*9216)
                  + (uint32_t)((lane & 15)*144) + (uint32_t)((lane >> 4)*16);

    #pragma unroll
    for (int ks = 0; ks < 4; ks++) {
        uint32_t a0[4], a1[4];
        ldsm4(a0, aoff + ks*32);
        ldsm4(a1, aoff + ks*32 + 16*528);
        #pragma unroll
        for (int dq = 0; dq < 4; dq++) {
            uint32_t bf[4];
            ldsm4t(bf, boff + ks*16*144 + dq*32);
            hmma(acc[0][dq*2],   a0, bf[0], bf[1]);
            hmma(acc[0][dq*2+1], a0, bf[2], bf[3]);
            hmma(acc[1][dq*2],   a1, bf[0], bf[1]);
            hmma(acc[1][dq*2+1], a1, bf[2], bf[3]);
        }
    }

    float sa = 1.f / (1.f + __expf(-alpha[hw]));
    float sb = 1.f / (1.f + __expf(-beta[hw]));
    #pragma unroll
    for (int mt = 0; mt < 2; mt++)
        #pragma unroll
        for (int j = 0; j < 8; j++) {
            int row = m_base + mt*16 + (lane >> 2);
            int col = hw*64 + j*8 + (lane & 3)*2;
            const float* c = acc[mt][j];
            {
                float2 xv = *(const float2*)(g_xv + gbase + (size_t)row*Dm + col);
                float2 o = {fmaf(sa, xv.x, sb*c[0]), fmaf(sa, xv.y, sb*c[1])};
                *(float2*)(out + gbase + (size_t)row*Dm + col) = o;
            }
            {
                float2 xv = *(const float2*)(g_xv + gbase + (size_t)(row+8)*Dm + col);
                float2 o = {fmaf(sa, xv.x, sb*c[2]), fmaf(sa, xv.y, sb*c[3])};
                *(float2*)(out + gbase + (size_t)(row+8)*Dm + col) = o;
            }
        }
}

extern "C" void kernel_launch(void* const* d_in, const int* in_sizes, int n_in,
                              void* d_out, int out_size) {
    const float* x     = (const float*)d_in[0];
    const float* z     = (const float*)d_in[1];
    const float* Wq    = (const float*)d_in[2];
    const float* bq    = (const float*)d_in[3];
    const float* K     = (const float*)d_in[4];
    const float* Wv    = (const float*)d_in[5];
    const float* bv    = (const float*)d_in[6];
    const float* alpha = (const float*)d_in[7];
    const float* beta  = (const float*)d_in[8];
    float* out = (float*)d_out;

    cudaFuncSetAttribute(kgemm_mma, cudaFuncAttributeMaxDynamicSharedMemorySize, SMEM_MMA);
    cudaFuncSetAttribute(kout,      cudaFuncAttributeMaxDynamicSharedMemorySize, SMEM_KOUT);

    kzero<<<512, 256>>>();
    kprep<<<Dm + 1, 256>>>(Wq, bq, K);
    kprep2<<<Dm, 256>>>(Wv);
    kgemm_mma<<<Mm/128, 512, SMEM_MMA>>>(z, bv, 1);   // attn first (produces rs)
    kgemm_mma<<<Mm/128, 512, SMEM_MMA>>>(x, bv, 0);   // xv + xvs (needs rs)
    kpool<<<dim3(8, Hh, Bz), 256>>>();
    kfin<<<8, 256>>>();
    kout<<<Mm/64, 256, SMEM_KOUT>>>(alpha, beta, out);
}